// round 3
// baseline (speedup 1.0000x reference)
#include <cuda_runtime.h>
#include <cuda_bf16.h>
#include <math_constants.h>

// Problem constants
#define B_  256
#define S_  128
#define D_  768
#define MASK_ID_ 103

// Scratch (no allocation allowed -> device globals)
__device__ float g_feats[B_ * 2 * D_];   // [att | mask_logits] per batch, 256 x 1536
__device__ float g_h[B_ * D_];           // tanh(dense) output, 256 x 768

__constant__ int c_label_ids[21] = {
    2307, 2204, 3835, 2157, 6581, 2986, 5151, 3893,
    7929, 24791, 8699, 4257, 16021, 6623,
    6659, 2919, 11771, 3532, 11325, 4997, 13135
};

__device__ __forceinline__ float warp_sum(float v) {
    #pragma unroll
    for (int o = 16; o; o >>= 1) v += __shfl_xor_sync(0xffffffffu, v, o);
    return v;
}
__device__ __forceinline__ float warp_max(float v) {
    #pragma unroll
    for (int o = 16; o; o >>= 1) v = fmaxf(v, __shfl_xor_sync(0xffffffffu, v, o));
    return v;
}

// ---------------------------------------------------------------------------
// Kernel 1: per-batch. mask_pos scan, mask_logits, scores softmax, att,
// category_out. Writes feats = [att | mask_logits] and category output.
// grid = 256 (one CTA per batch row), block = 256 (8 warps)
// ---------------------------------------------------------------------------
__global__ __launch_bounds__(256) void k1_attention(
    const float* __restrict__ bert,     // (B,S,D)
    const int*   __restrict__ input_ids,// (B,S)
    const int*   __restrict__ length,   // (B,)
    const float* __restrict__ senti_w,  // (2,D)
    const float* __restrict__ senti_b,  // (2,)
    float*       __restrict__ d_out,    // full output; category at [0:512]
    float*       __restrict__ feats)    // (B, 2D)
{
    const int b    = blockIdx.x;
    const int tid  = threadIdx.x;
    const int warp = tid >> 5;
    const int lane = tid & 31;

    __shared__ float ml[D_];      // mask_logits row
    __shared__ float sraw[S_];    // scores
    __shared__ float red[2];      // max, sum
    __shared__ int   mpos;

    if (tid == 0) mpos = 0x7fffffff;
    __syncthreads();

    // first position where input_ids == MASK_ID (guaranteed to exist)
    if (tid < S_ && input_ids[b * S_ + tid] == MASK_ID_) atomicMin(&mpos, tid);
    __syncthreads();
    const int mp = mpos;

    const float* base = bert + (size_t)b * (S_ * D_);

    // mask_logits -> smem
    for (int d = tid; d < D_; d += 256) ml[d] = base[mp * D_ + d];
    __syncthreads();

    // scores_raw[s] = dot(bert[b,s,:], ml)   8 warps x 16 s each
    #pragma unroll 1
    for (int i = 0; i < 16; i++) {
        const int s = warp + i * 8;
        const float* row = base + s * D_;
        float acc = 0.f;
        #pragma unroll
        for (int t = 0; t < 24; t++) {
            int d = lane + 32 * t;
            acc = fmaf(row[d], ml[d], acc);
        }
        acc = warp_sum(acc);
        if (lane == 0) sraw[s] = acc;
    }
    __syncthreads();

    const int L = length[b];

    // softmax stats over valid range [3, 3+L) by warp 0
    if (warp == 0) {
        float m = -CUDART_INF_F;
        #pragma unroll
        for (int i = 0; i < 4; i++) {
            int s = lane + 32 * i;
            if (s >= 3 && s < 3 + L) m = fmaxf(m, sraw[s]);
        }
        m = warp_max(m);
        float sum = 0.f;
        #pragma unroll
        for (int i = 0; i < 4; i++) {
            int s = lane + 32 * i;
            if (s >= 3 && s < 3 + L) sum += __expf(sraw[s] - m);
        }
        sum = warp_sum(sum);
        if (lane == 0) { red[0] = m; red[1] = sum; }
    }
    __syncthreads();
    {
        const float m   = red[0];
        const float inv = 1.0f / red[1];
        if (tid < S_) {
            int s = tid;
            bool v = (s >= 3) && (s < 3 + L);
            sraw[s] = v ? __expf(sraw[s] - m) * inv : 0.f;
        }
    }
    __syncthreads();

    // att[d] = sum_s scores[s] * bert[b,s,d]; write feats = [att | ml]
    float* fb = feats + (size_t)b * (2 * D_);
    #pragma unroll 1
    for (int q = 0; q < 3; q++) {
        const int d = tid + q * 256;
        float acc = 0.f;
        #pragma unroll 8
        for (int s = 0; s < S_; s++) {
            acc = fmaf(sraw[s], base[s * D_ + d], acc);
        }
        fb[d]      = acc;
        fb[D_ + d] = ml[d];
    }

    // category_out: pooler = bert[b,0,:]; warps 0,1 each do one class
    if (warp < 2) {
        float acc = 0.f;
        const float* sw = senti_w + warp * D_;
        #pragma unroll
        for (int t = 0; t < 24; t++) {
            int d = lane + 32 * t;
            acc = fmaf(base[d], sw[d], acc);
        }
        acc = warp_sum(acc);
        if (lane == 0) d_out[b * 2 + warp] = acc + senti_b[warp];
    }
}

// ---------------------------------------------------------------------------
// Kernel 2: h = tanh(feats @ dense_w^T + dense_b)
// M=256, N=768, K=1536.  A (M,K) row-major, Bw (N,K) row-major.
// Tiling: BM=32, BN=48, BK=32; 256 threads; 2x3 micro-tile; grid 8x16 = 128 CTAs
// ---------------------------------------------------------------------------
#define BM 32
#define BN 48
#define BK 32
#define KDIM 1536
#define NDIM 768

__global__ __launch_bounds__(256) void k2_dense(
    const float* __restrict__ A,     // feats (256,1536)
    const float* __restrict__ Bw,    // dense_w (768,1536)
    const float* __restrict__ bias,  // dense_b (768,)
    float*       __restrict__ H)     // (256,768)
{
    __shared__ float As[BM][BK];        // row-major, matches global
    __shared__ float Bs[BK][BN + 1];    // transposed, padded (49 -> conflict-free)

    const int m0  = blockIdx.x * BM;
    const int n0  = blockIdx.y * BN;
    const int tid = threadIdx.x;
    const int tx  = tid & 15;   // n direction: 16 x 3
    const int ty  = tid >> 4;   // m direction: 16 x 2

    float acc[2][3] = {{0.f,0.f,0.f},{0.f,0.f,0.f}};

    for (int k0 = 0; k0 < KDIM; k0 += BK) {
        // A tile: 32 rows x 32 k = 256 float4
        {
            int r = tid >> 3, c = tid & 7;
            float4 v = *(const float4*)(A + (size_t)(m0 + r) * KDIM + k0 + c * 4);
            *(float4*)&As[r][c * 4] = v;
        }
        // B tile: 48 rows x 32 k = 384 float4, transposed into Bs
        {
            int idx = tid;                      // 0..255
            int n = idx >> 3, c = idx & 7;
            float4 v = *(const float4*)(Bw + (size_t)(n0 + n) * KDIM + k0 + c * 4);
            Bs[c * 4 + 0][n] = v.x; Bs[c * 4 + 1][n] = v.y;
            Bs[c * 4 + 2][n] = v.z; Bs[c * 4 + 3][n] = v.w;
            if (tid < 128) {
                idx = tid + 256;                // 256..383
                n = idx >> 3; c = idx & 7;
                float4 v2 = *(const float4*)(Bw + (size_t)(n0 + n) * KDIM + k0 + c * 4);
                Bs[c * 4 + 0][n] = v2.x; Bs[c * 4 + 1][n] = v2.y;
                Bs[c * 4 + 2][n] = v2.z; Bs[c * 4 + 3][n] = v2.w;
            }
        }
        __syncthreads();

        #pragma unroll
        for (int k = 0; k < BK; k++) {
            float a0 = As[ty * 2 + 0][k];
            float a1 = As[ty * 2 + 1][k];
            float b0 = Bs[k][tx * 3 + 0];
            float b1 = Bs[k][tx * 3 + 1];
            float b2 = Bs[k][tx * 3 + 2];
            acc[0][0] = fmaf(a0, b0, acc[0][0]);
            acc[0][1] = fmaf(a0, b1, acc[0][1]);
            acc[0][2] = fmaf(a0, b2, acc[0][2]);
            acc[1][0] = fmaf(a1, b0, acc[1][0]);
            acc[1][1] = fmaf(a1, b1, acc[1][1]);
            acc[1][2] = fmaf(a1, b2, acc[1][2]);
        }
        __syncthreads();
    }

    #pragma unroll
    for (int i = 0; i < 2; i++) {
        int m = m0 + ty * 2 + i;
        #pragma unroll
        for (int j = 0; j < 3; j++) {
            int n = n0 + tx * 3 + j;
            H[(size_t)m * NDIM + n] = tanhf(acc[i][j] + bias[n]);
        }
    }
}

// ---------------------------------------------------------------------------
// Kernel 3: probs at the 21 label ids + tiny head GEMMs.
// out[b,i,j] = sum_l w_j[i,l] * tanh(h[b]·dec_w[id_{j,l}] + dec_b[id])
// grid = 256, block = 256
// ---------------------------------------------------------------------------
__global__ __launch_bounds__(256) void k3_decoder(
    const float* __restrict__ h,     // (256,768)
    const float* __restrict__ dec_w, // (V,768)
    const float* __restrict__ dec_b, // (V,)
    const float* __restrict__ w0,    // (2,8)
    const float* __restrict__ w1,    // (2,6)
    const float* __restrict__ w2,    // (2,7)
    float*       __restrict__ d_out)
{
    const int b    = blockIdx.x;
    const int tid  = threadIdx.x;
    const int warp = tid >> 5;
    const int lane = tid & 31;

    __shared__ float probs[21];
    const float* hb = h + (size_t)b * D_;

    for (int i = warp; i < 21; i += 8) {
        const int id = c_label_ids[i];
        const float* r = dec_w + (size_t)id * D_;
        float acc = 0.f;
        #pragma unroll
        for (int t = 0; t < 24; t++) {
            int d = lane + 32 * t;
            acc = fmaf(hb[d], r[d], acc);
        }
        acc = warp_sum(acc);
        if (lane == 0) probs[i] = tanhf(acc + dec_b[id]);
    }
    __syncthreads();

    if (tid < 6) {
        const int j = tid >> 1;   // which head (0..2)
        const int i = tid & 1;    // which row of w (0..1)
        const float* w   = (j == 0) ? w0 : (j == 1) ? w1 : w2;
        const int    off = (j == 0) ? 0  : (j == 1) ? 8  : 14;
        const int    n   = (j == 0) ? 8  : (j == 1) ? 6  : 7;
        float acc = 0.f;
        for (int l = 0; l < n; l++) acc += w[i * n + l] * probs[off + l];
        // out shape (B,2,3) row-major, after category_out (512 floats)
        d_out[512 + b * 6 + i * 3 + j] = acc;
    }
}

// ---------------------------------------------------------------------------
extern "C" void kernel_launch(void* const* d_in, const int* in_sizes, int n_in,
                              void* d_out, int out_size)
{
    const float* bert      = (const float*)d_in[0];   // (256,128,768) f32
    const int*   input_ids = (const int*)  d_in[1];   // (256,128) i32
    const int*   length    = (const int*)  d_in[2];   // (256,) i32
    const float* senti_w   = (const float*)d_in[3];   // (2,768)
    const float* senti_b   = (const float*)d_in[4];   // (2,)
    const float* dense_w   = (const float*)d_in[5];   // (768,1536)
    const float* dense_b   = (const float*)d_in[6];   // (768,)
    const float* dec_w     = (const float*)d_in[7];   // (30522,768)
    const float* dec_b     = (const float*)d_in[8];   // (30522,)
    const float* w0        = (const float*)d_in[9];   // (2,8)
    const float* w1        = (const float*)d_in[10];  // (2,6)
    const float* w2        = (const float*)d_in[11];  // (2,7)
    float* out = (float*)d_out;

    float* feats; cudaGetSymbolAddress((void**)&feats, g_feats);
    float* hbuf;  cudaGetSymbolAddress((void**)&hbuf,  g_h);

    k1_attention<<<B_, 256>>>(bert, input_ids, length, senti_w, senti_b, out, feats);
    k2_dense<<<dim3(B_ / BM, NDIM / BN), 256>>>(feats, dense_w, dense_b, hbuf);
    k3_decoder<<<B_, 256>>>(hbuf, dec_w, dec_b, w0, w1, w2, out);
}